// round 8
// baseline (speedup 1.0000x reference)
#include <cuda_runtime.h>
#include <cuda_fp16.h>
#include <math.h>

#define NN 100000
#define EE 1600000

typedef unsigned long long ull;

// ---------------- device scratch (no allocations allowed) ----------------
__device__ int   g_is64;
__device__ int   g_count[NN];
__device__ int   g_rowptr[NN + 1];
__device__ int   g_cursor[NN];
__device__ int   g_blocksums[256];
__device__ float g_dinv[NN];
__device__ int2  g_epack[EE];              // (src, norm bits) packed
__device__ __half g_hlin[NN * 64];         // fp16 GCN linear output (12.8MB)
__device__ float g_h[NN * 64];             // fp32 residual stream
__device__ __half g_hg[NN * 256];          // fp16 GAT value matrix (51MB, L2-resident)
__device__ float g_asrc[NN * 4];
__device__ float g_adst[NN * 4];
__device__ float g_hatt[NN * 256];
__device__ float g_Wa[64 * 8];             // composite att weights: [k][0..3]=src, [4..7]=dst

// ---------------- f32x2 packed-FMA helpers (sm_103a FFMA2) ----------------
__device__ __forceinline__ ull pack2(float x, float y) {
    ull r; asm("mov.b64 %0, {%1, %2};" : "=l"(r) : "f"(x), "f"(y)); return r;
}
__device__ __forceinline__ float2 unpack2(ull v) {
    float2 r; asm("mov.b64 {%0, %1}, %2;" : "=f"(r.x), "=f"(r.y) : "l"(v)); return r;
}
__device__ __forceinline__ ull fma2(ull a, ull b, ull c) {
    ull d; asm("fma.rn.f32x2 %0, %1, %2, %3;" : "=l"(d) : "l"(a), "l"(b), "l"(c)); return d;
}

__device__ __forceinline__ int ld_edge(const void* ei, int is64, long long idx) {
    if (is64) return (int)((const long long*)ei)[idx];
    return ((const int*)ei)[idx];
}

// ---------------- dtype detection ----------------
__global__ void k_detect(const int* __restrict__ ei) {
    int all0 = 1;
    for (int i = 1; i < 32; i += 2)
        if (ei[i] != 0) { all0 = 0; break; }
    g_is64 = all0;
}

// ---------------- CSR build ----------------
__global__ void k_zero(int n) {
    int i = blockIdx.x * blockDim.x + threadIdx.x;
    if (i < n) g_count[i] = 0;
}

__global__ void k_count(const void* __restrict__ ei, int e) {
    int i = blockIdx.x * blockDim.x + threadIdx.x;
    if (i < e) {
        int is64 = g_is64;
        int d = ld_edge(ei, is64, (long long)e + i);
        atomicAdd(&g_count[d], 1);
    }
}

__global__ void k_scan1(int n) {
    __shared__ int s[512];
    int tid = threadIdx.x;
    int i = blockIdx.x * 512 + tid;
    int v = (i < n) ? g_count[i] : 0;
    s[tid] = v;
    __syncthreads();
    for (int off = 1; off < 512; off <<= 1) {
        int t = (tid >= off) ? s[tid - off] : 0;
        __syncthreads();
        s[tid] += t;
        __syncthreads();
    }
    if (i < n) g_rowptr[i] = s[tid] - v;
    if (tid == 511) g_blocksums[blockIdx.x] = s[511];
}

__global__ void k_scan2(int nb) {
    int run = 0;
    for (int b = 0; b < nb; ++b) { int t = g_blocksums[b]; g_blocksums[b] = run; run += t; }
}

__global__ void k_scan3(int n, int e) {
    int i = blockIdx.x * blockDim.x + threadIdx.x;
    if (i < n) {
        int rp = g_rowptr[i] + g_blocksums[i >> 9];
        g_rowptr[i] = rp;
        g_cursor[i] = rp;
        g_dinv[i] = rsqrtf((float)(g_count[i] + 1));
        if (i == 0) g_rowptr[n] = e;
    }
}

__global__ void k_scatter(const void* __restrict__ ei, int e) {
    int i = blockIdx.x * blockDim.x + threadIdx.x;
    if (i < e) {
        int is64 = g_is64;
        int s = ld_edge(ei, is64, i);
        int d = ld_edge(ei, is64, (long long)e + i);
        int p = atomicAdd(&g_cursor[d], 1);
        g_epack[p] = make_int2(s, __float_as_int(g_dinv[s] * g_dinv[d]));
    }
}

// ---------------- layer-1 GEMM: hlin = X[N,8] @ W[8,64] (fp16 out) ----------------
__global__ void k_gemm8(const float* __restrict__ X, const float* __restrict__ W, int n) {
    __shared__ float sx[4][8];
    int tid = threadIdx.x;
    int l = tid >> 6, col = tid & 63;
    int base = blockIdx.x * 4;
    if (tid < 32) {
        int r = base + (tid >> 3);
        sx[tid >> 3][tid & 7] = (r < n) ? X[r * 8 + (tid & 7)] : 0.f;
    }
    __syncthreads();
    int node = base + l;
    if (node < n) {
        float acc = 0.f;
#pragma unroll
        for (int k = 0; k < 8; ++k) acc += sx[l][k] * W[k * 64 + col];
        g_hlin[node * 64 + col] = __float2half(acc);
    }
}

// ---------------- GCN GEMM: hlin = g_h @ W[64,64] via FFMA2, 8 nodes/tile ----------------
__global__ void __launch_bounds__(256) k_gemm64(const float* __restrict__ W, int n) {
    int tid = threadIdx.x;
    int c2 = tid & 31;      // cols 2c2, 2c2+1
    int l = tid >> 5;       // node slot 0..7 (== warp id -> uniform per warp)
    ull w2[64];
#pragma unroll
    for (int k = 0; k < 64; ++k) {
        float2 wv = *(const float2*)&W[k * 64 + 2 * c2];
        w2[k] = pack2(wv.x, wv.y);
    }
    __shared__ __align__(16) float2 sxd[8][64];   // duplicated activations
    for (int base = blockIdx.x * 8; base < n; base += gridDim.x * 8) {
        __syncthreads();
        {
            int nd = tid >> 5, kk = (tid & 31) * 2;
            float2 v = (base + nd < n) ? *(const float2*)&g_h[(base + nd) * 64 + kk]
                                       : make_float2(0.f, 0.f);
            sxd[nd][kk]     = make_float2(v.x, v.x);
            sxd[nd][kk + 1] = make_float2(v.y, v.y);
        }
        __syncthreads();
        int node = base + l;
        if (node < n) {
            ull acc = pack2(0.f, 0.f);
#pragma unroll
            for (int kk = 0; kk < 32; ++kk) {
                ulonglong2 a2 = *(const ulonglong2*)&sxd[l][2 * kk];
                acc = fma2(a2.x, w2[2 * kk], acc);
                acc = fma2(a2.y, w2[2 * kk + 1], acc);
            }
            float2 r = unpack2(acc);
            *(__half2*)&g_hlin[node * 64 + 2 * c2] = __floats2half2_rn(r.x, r.y);
        }
    }
}

// ---------------- GCN aggregation: warp/node, fp16 gathers, 8-deep prefetch ----------------
__global__ void k_gcn_agg(const float* __restrict__ b, int n, int residual) {
    int tid = threadIdx.x, warp = tid >> 5, lane = tid & 31;
    int node = blockIdx.x * 8 + warp;
    if (node >= n) return;
    float di = g_dinv[node];
    float2 self = __half22float2(*(const __half2*)&g_hlin[node * 64 + 2 * lane]);
    float accx = di * di * self.x, accy = di * di * self.y;
    int beg = g_rowptr[node], end = g_rowptr[node + 1];
    int j = beg;
    for (; j + 7 < end; j += 8) {
        int2 ep[8];
#pragma unroll
        for (int q = 0; q < 8; ++q) ep[q] = g_epack[j + q];
#pragma unroll
        for (int q = 0; q < 8; ++q) {
            float w = __int_as_float(ep[q].y);
            float2 v = __half22float2(*(const __half2*)&g_hlin[ep[q].x * 64 + 2 * lane]);
            accx += w * v.x; accy += w * v.y;
        }
    }
    for (; j < end; ++j) {
        int2 ep = g_epack[j];
        float w = __int_as_float(ep.y);
        float2 v = __half22float2(*(const __half2*)&g_hlin[ep.x * 64 + 2 * lane]);
        accx += w * v.x; accy += w * v.y;
    }
    float2 bb = ((const float2*)b)[lane];
    float vx = fmaxf(accx + bb.x, 0.f), vy = fmaxf(accy + bb.y, 0.f);
    float2* H = (float2*)g_h;
    if (residual) {
        float2 p = H[node * 32 + lane];
        H[node * 32 + lane] = make_float2(p.x + vx, p.y + vy);
    } else {
        H[node * 32 + lane] = make_float2(vx, vy);
    }
}

// ---------------- composite attention weights: Wa = wg . att  (64x8) ----------------
__global__ void k_att_pre(const float* __restrict__ wg,
                          const float* __restrict__ att_s,
                          const float* __restrict__ att_d) {
    int t = threadIdx.x;       // 512 threads: o=t&7, k=t>>3
    int o = t & 7, k = t >> 3;
    int h = o & 3;
    const float* att = (o < 4) ? att_s : att_d;
    float s = 0.f;
#pragma unroll 8
    for (int c = 0; c < 64; ++c) s += wg[k * 256 + h * 64 + c] * att[h * 64 + c];
    g_Wa[k * 8 + o] = s;
}

// ---------------- GAT linear: hg = g_h @ wg[64,256] via FFMA2 (fp16 out) ----------------
__global__ void __launch_bounds__(256) k_gat_gemm(const float* __restrict__ wg, int n) {
    int tid = threadIdx.x;
    int c2 = tid & 127;     // cols 2c2, 2c2+1
    int q = tid >> 7;       // node slot 0..1 (uniform per warp)
    ull w2[64];
#pragma unroll
    for (int k = 0; k < 64; ++k) {
        float2 wv = *(const float2*)&wg[k * 256 + 2 * c2];
        w2[k] = pack2(wv.x, wv.y);
    }
    __shared__ __align__(16) float2 sxd[2][64];
    for (int base = blockIdx.x * 2; base < n; base += gridDim.x * 2) {
        __syncthreads();
        if (tid < 64) {
            int nd = tid >> 5, kk = (tid & 31) * 2;
            float2 v = (base + nd < n) ? *(const float2*)&g_h[(base + nd) * 64 + kk]
                                       : make_float2(0.f, 0.f);
            sxd[nd][kk]     = make_float2(v.x, v.x);
            sxd[nd][kk + 1] = make_float2(v.y, v.y);
        }
        __syncthreads();
        int node = base + q;
        if (node < n) {
            ull acc = pack2(0.f, 0.f);
#pragma unroll
            for (int kk = 0; kk < 32; ++kk) {
                ulonglong2 a2 = *(const ulonglong2*)&sxd[q][2 * kk];
                acc = fma2(a2.x, w2[2 * kk], acc);
                acc = fma2(a2.y, w2[2 * kk + 1], acc);
            }
            float2 r = unpack2(acc);
            *(__half2*)&g_hg[node * 256 + 2 * c2] = __floats2half2_rn(r.x, r.y);
        }
    }
}

// ---------------- attention coefficients: asrc/adst = g_h @ Wa (warp per node) ----------------
__global__ void k_att(int n) {
    int tid = threadIdx.x, warp = tid >> 5, lane = tid & 31;
    int node = blockIdx.x * 8 + warp;
    if (node >= n) return;
    float2 hv = *(const float2*)&g_h[node * 64 + 2 * lane];
    float r[8];
#pragma unroll
    for (int o = 0; o < 8; ++o) {
        r[o] = hv.x * g_Wa[(2 * lane) * 8 + o] + hv.y * g_Wa[(2 * lane + 1) * 8 + o];
#pragma unroll
        for (int off = 16; off > 0; off >>= 1)
            r[o] += __shfl_xor_sync(0xffffffffu, r[o], off);
    }
    if (lane < 4)      g_asrc[node * 4 + lane] = r[lane];
    else if (lane < 8) g_adst[node * 4 + lane - 4] = r[lane];
}

// ---------------- GAT softmax + aggregation: 4 nodes/block x 64 thr, fp16 gathers ----------------
__device__ __forceinline__ float lrelu(float e) { return e > 0.f ? e : 0.2f * e; }

__device__ __forceinline__ float4 wmax4(float4 v) {
#pragma unroll
    for (int o = 16; o > 0; o >>= 1) {
        v.x = fmaxf(v.x, __shfl_xor_sync(0xffffffffu, v.x, o));
        v.y = fmaxf(v.y, __shfl_xor_sync(0xffffffffu, v.y, o));
        v.z = fmaxf(v.z, __shfl_xor_sync(0xffffffffu, v.z, o));
        v.w = fmaxf(v.w, __shfl_xor_sync(0xffffffffu, v.w, o));
    }
    return v;
}

__device__ __forceinline__ float4 wsum4(float4 v) {
#pragma unroll
    for (int o = 16; o > 0; o >>= 1) {
        v.x += __shfl_xor_sync(0xffffffffu, v.x, o);
        v.y += __shfl_xor_sync(0xffffffffu, v.y, o);
        v.z += __shfl_xor_sync(0xffffffffu, v.z, o);
        v.w += __shfl_xor_sync(0xffffffffu, v.w, o);
    }
    return v;
}

__global__ void __launch_bounds__(256) k_gat_agg(const float* __restrict__ bg, int n) {
    int tid = threadIdx.x;
    int g = tid >> 6, t = tid & 63;
    int h = t >> 4;
    int wig = (t >> 5) & 1;
    int lane = tid & 31;
    int node = blockIdx.x * 4 + g;
    bool valid = node < n;

    __shared__ float4 s_ex4[4][64];
    __shared__ int    s_srcv[4][64];
    __shared__ float4 s_red[4][2];

    int beg = 0, m = 0;
    if (valid) { beg = g_rowptr[node]; m = g_rowptr[node + 1] - beg + 1; }

    float4 ad = valid ? ((const float4*)g_adst)[node] : make_float4(0, 0, 0, 0);

    float4 mx = make_float4(-1e30f, -1e30f, -1e30f, -1e30f);
    for (int j = t; j < m; j += 64) {
        int s = (j < m - 1) ? g_epack[beg + j].x : node;
        float4 as = ((const float4*)g_asrc)[s];
        mx.x = fmaxf(mx.x, lrelu(as.x + ad.x));
        mx.y = fmaxf(mx.y, lrelu(as.y + ad.y));
        mx.z = fmaxf(mx.z, lrelu(as.z + ad.z));
        mx.w = fmaxf(mx.w, lrelu(as.w + ad.w));
    }
    mx = wmax4(mx);
    if (lane == 0) s_red[g][wig] = mx;
    __syncthreads();
    {
        float4 a = s_red[g][0], b2 = s_red[g][1];
        mx.x = fmaxf(a.x, b2.x); mx.y = fmaxf(a.y, b2.y);
        mx.z = fmaxf(a.z, b2.z); mx.w = fmaxf(a.w, b2.w);
    }

    float4 acc = make_float4(0, 0, 0, 0);
    float4 den = make_float4(0, 0, 0, 0);
    int ntiles = (m + 63) / 64;
    __shared__ int s_nt[4];
    if (t == 0) s_nt[g] = ntiles;
    __syncthreads();
    int ntmax = max(max(s_nt[0], s_nt[1]), max(s_nt[2], s_nt[3]));

    const uint2* hgq = (const uint2*)g_hg;   // 8B = 4 fp16 per thread
    const float* s_exf = (const float*)&s_ex4[0][0];
    for (int tile = 0; tile < ntmax; ++tile) {
        __syncthreads();
        int j = tile * 64 + t;
        if (j < m) {
            int s = (j < m - 1) ? g_epack[beg + j].x : node;
            s_srcv[g][t] = s;
            float4 as = ((const float4*)g_asrc)[s];
            float4 ex;
            ex.x = __expf(lrelu(as.x + ad.x) - mx.x);
            ex.y = __expf(lrelu(as.y + ad.y) - mx.y);
            ex.z = __expf(lrelu(as.z + ad.z) - mx.z);
            ex.w = __expf(lrelu(as.w + ad.w) - mx.w);
            den.x += ex.x; den.y += ex.y; den.z += ex.z; den.w += ex.w;
            s_ex4[g][t] = ex;
        }
        __syncthreads();
        int tcnt = min(64, m - tile * 64);
#pragma unroll 4
        for (int jj = 0; jj < tcnt; ++jj) {
            float exv = s_exf[g * 256 + jj * 4 + h];
            uint2 raw = hgq[(unsigned)s_srcv[g][jj] * 64u + t];
            float2 f0 = __half22float2(*(const __half2*)&raw.x);
            float2 f1 = __half22float2(*(const __half2*)&raw.y);
            acc.x += exv * f0.x; acc.y += exv * f0.y;
            acc.z += exv * f1.x; acc.w += exv * f1.y;
        }
    }
    den = wsum4(den);
    if (lane == 0) s_red[g][wig] = den;
    __syncthreads();
    float4 d0 = s_red[g][0], d1 = s_red[g][1];
    float4 dt = make_float4(d0.x + d1.x, d0.y + d1.y, d0.z + d1.z, d0.w + d1.w);
    float denh = (h == 0) ? dt.x : (h == 1) ? dt.y : (h == 2) ? dt.z : dt.w;
    if (valid) {
        float4 bgv = ((const float4*)bg)[t];
        float inv = 1.f / (denh + 1e-16f);
        float4 o;
        o.x = acc.x * inv + bgv.x; o.y = acc.y * inv + bgv.y;
        o.z = acc.z * inv + bgv.z; o.w = acc.w * inv + bgv.w;
        ((float4*)g_hatt)[(unsigned)node * 64u + t] = o;
    }
}

// ---------------- classifier: transposed-A tiled SGEMM w/ FFMA2 + log_softmax ----------------
__global__ void __launch_bounds__(256) k_classifier(
    const float* __restrict__ wc1, const float* __restrict__ bc1,
    const float* __restrict__ wc2, const float* __restrict__ bc2,
    float* __restrict__ out, int n) {
    extern __shared__ float sm[];
    float* sW  = sm;            // [256][64] = 16384 floats
    float* sAT = sm + 16384;    // [256][68] = 17408 floats (transposed A, padded; reused as sZ)
    __shared__ float sWc2[192];
    __shared__ float sB[64];
    __shared__ float sB2[3];
    __shared__ float sLg[192];
    __shared__ float sLse[64];

    int tid = threadIdx.x;
    int base = blockIdx.x * 64;

    for (int i = tid; i < 4096; i += 256) ((float4*)sW)[i] = ((const float4*)wc1)[i];
    if (tid < 192) sWc2[tid] = wc2[tid];
    if (tid < 64) sB[tid] = bc1[tid];
    if (tid < 3) sB2[tid] = bc2[tid];

    // load + transpose A tile: sAT[k][node], padded stride 68
    const float4* hatt4 = (const float4*)g_hatt;
    for (int i = tid; i < 4096; i += 256) {
        int r = i >> 6, c4 = i & 63;
        float4 v = make_float4(0, 0, 0, 0);
        if (base + r < n) v = hatt4[(unsigned)(base + r) * 64u + c4];
        sAT[(4 * c4 + 0) * 68 + r] = v.x;
        sAT[(4 * c4 + 1) * 68 + r] = v.y;
        sAT[(4 * c4 + 2) * 68 + r] = v.z;
        sAT[(4 * c4 + 3) * 68 + r] = v.w;
    }
    __syncthreads();

    int colq = tid & 15;    // cols 4colq..+3
    int nodeq = tid >> 4;   // nodes 4nodeq..+3 (2 packed pairs)
    ull az2[2][4];
#pragma unroll
    for (int p = 0; p < 2; ++p)
#pragma unroll
        for (int c = 0; c < 4; ++c) az2[p][c] = pack2(0.f, 0.f);

    const float4* sW4 = (const float4*)sW;
#pragma unroll 4
    for (int k = 0; k < 256; ++k) {
        ulonglong2 ap = *(const ulonglong2*)&sAT[k * 68 + nodeq * 4];  // (n0,n1),(n2,n3)
        float4 wv = sW4[k * 16 + colq];
        ull w0 = pack2(wv.x, wv.x), w1 = pack2(wv.y, wv.y);
        ull w2d = pack2(wv.z, wv.z), w3 = pack2(wv.w, wv.w);
        az2[0][0] = fma2(ap.x, w0, az2[0][0]); az2[0][1] = fma2(ap.x, w1, az2[0][1]);
        az2[0][2] = fma2(ap.x, w2d, az2[0][2]); az2[0][3] = fma2(ap.x, w3, az2[0][3]);
        az2[1][0] = fma2(ap.y, w0, az2[1][0]); az2[1][1] = fma2(ap.y, w1, az2[1][1]);
        az2[1][2] = fma2(ap.y, w2d, az2[1][2]); az2[1][3] = fma2(ap.y, w3, az2[1][3]);
    }
    __syncthreads();   // done reading sAT; reuse as sZ [64][65]
    float* sZ = sAT;
#pragma unroll
    for (int p = 0; p < 2; ++p)
#pragma unroll
        for (int c = 0; c < 4; ++c) {
            float2 v = unpack2(az2[p][c]);
            float bb = sB[colq * 4 + c];
            sZ[(nodeq * 4 + 2 * p + 0) * 65 + colq * 4 + c] = fmaxf(v.x + bb, 0.f);
            sZ[(nodeq * 4 + 2 * p + 1) * 65 + colq * 4 + c] = fmaxf(v.y + bb, 0.f);
        }
    __syncthreads();

    if (tid < 192) {
        int r = tid / 3, o = tid - 3 * r;
        float a = sB2[o];
#pragma unroll 8
        for (int c = 0; c < 64; ++c) a += sZ[r * 65 + c] * sWc2[c * 3 + o];
        sLg[tid] = a;
    }
    __syncthreads();
    if (tid < 64) {
        float l0 = sLg[tid * 3 + 0], l1 = sLg[tid * 3 + 1], l2 = sLg[tid * 3 + 2];
        float mm = fmaxf(l0, fmaxf(l1, l2));
        sLse[tid] = mm + logf(__expf(l0 - mm) + __expf(l1 - mm) + __expf(l2 - mm));
    }
    __syncthreads();
    int nvalid = n - base; if (nvalid > 64) nvalid = 64;
    if (tid < nvalid * 3) out[base * 3 + tid] = sLg[tid] - sLse[tid / 3];
}

// ---------------- launch ----------------
extern "C" void kernel_launch(void* const* d_in, const int* in_sizes, int n_in,
                              void* d_out, int out_size) {
    const float* x     = (const float*)d_in[0];
    const void*  ei    = (const void*)d_in[1];
    const float* w1    = (const float*)d_in[2];
    const float* b1    = (const float*)d_in[3];
    const float* w2    = (const float*)d_in[4];
    const float* b2    = (const float*)d_in[5];
    const float* w3    = (const float*)d_in[6];
    const float* b3    = (const float*)d_in[7];
    const float* wg    = (const float*)d_in[8];
    const float* bg    = (const float*)d_in[9];
    const float* att_s = (const float*)d_in[10];
    const float* att_d = (const float*)d_in[11];
    const float* wc1   = (const float*)d_in[12];
    const float* bc1   = (const float*)d_in[13];
    const float* wc2   = (const float*)d_in[14];
    const float* bc2   = (const float*)d_in[15];
    float* out = (float*)d_out;

    int n = in_sizes[0] / 8;
    int e = in_sizes[1] / 2;

    int nb512 = (n + 511) / 512;

    k_detect<<<1, 1>>>((const int*)ei);
    k_zero<<<(n + 255) / 256, 256>>>(n);
    k_count<<<(e + 255) / 256, 256>>>(ei, e);
    k_scan1<<<nb512, 512>>>(n);
    k_scan2<<<1, 1>>>(nb512);
    k_scan3<<<(n + 255) / 256, 256>>>(n, e);
    k_scatter<<<(e + 255) / 256, 256>>>(ei, e);

    // GCN layer 1
    k_gemm8<<<(n + 3) / 4, 256>>>(x, w1, n);
    k_gcn_agg<<<(n + 7) / 8, 256>>>(b1, n, 0);
    // GCN layer 2 (residual)
    k_gemm64<<<148, 256>>>(w2, n);
    k_gcn_agg<<<(n + 7) / 8, 256>>>(b2, n, 1);
    // GCN layer 3 (residual)
    k_gemm64<<<148, 256>>>(w3, n);
    k_gcn_agg<<<(n + 7) / 8, 256>>>(b3, n, 1);
    // GAT
    k_att_pre<<<1, 512>>>(wg, att_s, att_d);
    k_gat_gemm<<<148, 256>>>(wg, n);
    k_att<<<(n + 7) / 8, 256>>>(n);
    k_gat_agg<<<(n + 3) / 4, 256>>>(bg, n);
    // classifier (135168 B dynamic smem)
    static int smem_set = 0;
    if (!smem_set) {
        cudaFuncSetAttribute(k_classifier, cudaFuncAttributeMaxDynamicSharedMemorySize, 135168);
        smem_set = 1;
    }
    k_classifier<<<(n + 63) / 64, 256, 135168>>>(wc1, bc1, wc2, bc2, out, n);
}

// round 9
// speedup vs baseline: 1.0722x; 1.0722x over previous
#include <cuda_runtime.h>
#include <cuda_fp16.h>
#include <math.h>

#define NN 100000
#define EE 1600000

// ---------------- device scratch (no allocations allowed) ----------------
__device__ int   g_is64;
__device__ int   g_count[NN];
__device__ int   g_rowptr[NN + 1];
__device__ int   g_cursor[NN];
__device__ int   g_blocksums[256];
__device__ float g_dinv[NN];
__device__ int2  g_epack[EE];              // (src, norm bits)
__device__ __half g_hlin[NN * 64];         // fp16 GCN linear output (12.8MB)
__device__ float g_h[NN * 64];             // fp32 residual stream
__device__ __half g_hg[NN * 256];          // fp16 GAT value matrix (51MB)
__device__ float g_asrc[NN * 4];
__device__ float g_adst[NN * 4];
__device__ float g_hatt[NN * 256];
__device__ float g_Wa[64 * 8];             // composite att weights

__device__ __forceinline__ int ld_edge(const void* ei, int is64, long long idx) {
    if (is64) return (int)((const long long*)ei)[idx];
    return ((const int*)ei)[idx];
}

// ---------------- dtype detection ----------------
__global__ void k_detect(const int* __restrict__ ei) {
    int all0 = 1;
    for (int i = 1; i < 32; i += 2)
        if (ei[i] != 0) { all0 = 0; break; }
    g_is64 = all0;
}

// ---------------- CSR build ----------------
__global__ void k_zero(int n) {
    int i = blockIdx.x * blockDim.x + threadIdx.x;
    if (i < n) g_count[i] = 0;
}

__global__ void k_count(const void* __restrict__ ei, int e) {
    int i = blockIdx.x * blockDim.x + threadIdx.x;
    if (i < e) {
        int is64 = g_is64;
        int d = ld_edge(ei, is64, (long long)e + i);
        atomicAdd(&g_count[d], 1);
    }
}

__global__ void k_scan1(int n) {
    __shared__ int s[512];
    int tid = threadIdx.x;
    int i = blockIdx.x * 512 + tid;
    int v = (i < n) ? g_count[i] : 0;
    s[tid] = v;
    __syncthreads();
    for (int off = 1; off < 512; off <<= 1) {
        int t = (tid >= off) ? s[tid - off] : 0;
        __syncthreads();
        s[tid] += t;
        __syncthreads();
    }
    if (i < n) g_rowptr[i] = s[tid] - v;
    if (tid == 511) g_blocksums[blockIdx.x] = s[511];
}

__global__ void k_scan2(int nb) {
    int run = 0;
    for (int b = 0; b < nb; ++b) { int t = g_blocksums[b]; g_blocksums[b] = run; run += t; }
}

__global__ void k_scan3(int n, int e) {
    int i = blockIdx.x * blockDim.x + threadIdx.x;
    if (i < n) {
        int rp = g_rowptr[i] + g_blocksums[i >> 9];
        g_rowptr[i] = rp;
        g_cursor[i] = rp;
        g_dinv[i] = rsqrtf((float)(g_count[i] + 1));
        if (i == 0) g_rowptr[n] = e;
    }
}

__global__ void k_scatter(const void* __restrict__ ei, int e) {
    int i = blockIdx.x * blockDim.x + threadIdx.x;
    if (i < e) {
        int is64 = g_is64;
        int s = ld_edge(ei, is64, i);
        int d = ld_edge(ei, is64, (long long)e + i);
        int p = atomicAdd(&g_cursor[d], 1);
        g_epack[p] = make_int2(s, __float_as_int(g_dinv[s] * g_dinv[d]));
    }
}

// ---------------- layer-1 GEMM: hlin = X[N,8] @ W[8,64] (fp16 out) ----------------
__global__ void k_gemm8(const float* __restrict__ X, const float* __restrict__ W, int n) {
    __shared__ float sx[4][8];
    int tid = threadIdx.x;
    int l = tid >> 6, col = tid & 63;
    int base = blockIdx.x * 4;
    if (tid < 32) {
        int r = base + (tid >> 3);
        sx[tid >> 3][tid & 7] = (r < n) ? X[r * 8 + (tid & 7)] : 0.f;
    }
    __syncthreads();
    int node = base + l;
    if (node < n) {
        float acc = 0.f;
#pragma unroll
        for (int k = 0; k < 8; ++k) acc += sx[l][k] * W[k * 64 + col];
        g_hlin[node * 64 + col] = __float2half(acc);
    }
}

// ---------------- GCN GEMM: hlin = g_h @ W[64,64], scalar W col in regs ----------------
__global__ void __launch_bounds__(256) k_gemm64(const float* __restrict__ W, int n) {
    float w[64];
    int tid = threadIdx.x;
    int l = tid >> 6, col = tid & 63;
#pragma unroll
    for (int k = 0; k < 64; ++k) w[k] = W[k * 64 + col];
    __shared__ float sx[4][64];
    for (int base = blockIdx.x * 4; base < n; base += gridDim.x * 4) {
        __syncthreads();
        int r = base + (tid >> 6);
        sx[tid >> 6][tid & 63] = (r < n) ? g_h[r * 64 + (tid & 63)] : 0.f;
        __syncthreads();
        int node = base + l;
        if (node < n) {
            float acc = 0.f;
#pragma unroll
            for (int k = 0; k < 64; ++k) acc += sx[l][k] * w[k];
            g_hlin[node * 64 + col] = __float2half(acc);
        }
    }
}

// ---------------- GCN aggregation: warp/node, fp16 gathers, 8-deep prefetch ----------------
__global__ void k_gcn_agg(const float* __restrict__ b, int n, int residual) {
    int tid = threadIdx.x, warp = tid >> 5, lane = tid & 31;
    int node = blockIdx.x * 8 + warp;
    if (node >= n) return;
    float di = g_dinv[node];
    float2 self = __half22float2(*(const __half2*)&g_hlin[node * 64 + 2 * lane]);
    float accx = di * di * self.x, accy = di * di * self.y;
    int beg = g_rowptr[node], end = g_rowptr[node + 1];
    int j = beg;
    for (; j + 7 < end; j += 8) {
        int2 ep[8];
#pragma unroll
        for (int q = 0; q < 8; ++q) ep[q] = g_epack[j + q];
#pragma unroll
        for (int q = 0; q < 8; ++q) {
            float w = __int_as_float(ep[q].y);
            float2 v = __half22float2(*(const __half2*)&g_hlin[ep[q].x * 64 + 2 * lane]);
            accx += w * v.x; accy += w * v.y;
        }
    }
    for (; j < end; ++j) {
        int2 ep = g_epack[j];
        float w = __int_as_float(ep.y);
        float2 v = __half22float2(*(const __half2*)&g_hlin[ep.x * 64 + 2 * lane]);
        accx += w * v.x; accy += w * v.y;
    }
    float2 bb = ((const float2*)b)[lane];
    float vx = fmaxf(accx + bb.x, 0.f), vy = fmaxf(accy + bb.y, 0.f);
    float2* H = (float2*)g_h;
    if (residual) {
        float2 p = H[node * 32 + lane];
        H[node * 32 + lane] = make_float2(p.x + vx, p.y + vy);
    } else {
        H[node * 32 + lane] = make_float2(vx, vy);
    }
}

// ---------------- composite attention weights: Wa = wg . att  (64x8) ----------------
__global__ void k_att_pre(const float* __restrict__ wg,
                          const float* __restrict__ att_s,
                          const float* __restrict__ att_d) {
    int t = threadIdx.x;       // 512 threads: o=t&7, k=t>>3
    int o = t & 7, k = t >> 3;
    int h = o & 3;
    const float* att = (o < 4) ? att_s : att_d;
    float s = 0.f;
#pragma unroll 8
    for (int c = 0; c < 64; ++c) s += wg[k * 256 + h * 64 + c] * att[h * 64 + c];
    g_Wa[k * 8 + o] = s;
}

// ---------------- GAT linear: hg = g_h @ wg[64,256], scalar W col in regs ----------------
__global__ void __launch_bounds__(256) k_gat_gemm(const float* __restrict__ wg, int n) {
    float w[64];
    int tid = threadIdx.x;
#pragma unroll
    for (int k = 0; k < 64; ++k) w[k] = wg[k * 256 + tid];
    __shared__ float sh[4][64];
    for (int base = blockIdx.x * 4; base < n; base += gridDim.x * 4) {
        __syncthreads();
        int r = base + (tid >> 6);
        sh[tid >> 6][tid & 63] = (r < n) ? g_h[r * 64 + (tid & 63)] : 0.f;
        __syncthreads();
#pragma unroll
        for (int q = 0; q < 4; ++q) {
            int node = base + q;
            if (node >= n) break;
            float acc = 0.f;
#pragma unroll
            for (int k = 0; k < 64; ++k) acc += sh[q][k] * w[k];
            g_hg[node * 256 + tid] = __float2half(acc);
        }
    }
}

// ---------------- attention coefficients: asrc/adst = g_h @ Wa (warp per node) ----------------
__global__ void k_att(int n) {
    int tid = threadIdx.x, warp = tid >> 5, lane = tid & 31;
    int node = blockIdx.x * 8 + warp;
    if (node >= n) return;
    float2 hv = *(const float2*)&g_h[node * 64 + 2 * lane];
    float r[8];
#pragma unroll
    for (int o = 0; o < 8; ++o) {
        r[o] = hv.x * g_Wa[(2 * lane) * 8 + o] + hv.y * g_Wa[(2 * lane + 1) * 8 + o];
#pragma unroll
        for (int off = 16; off > 0; off >>= 1)
            r[o] += __shfl_xor_sync(0xffffffffu, r[o], off);
    }
    if (lane < 4)      g_asrc[node * 4 + lane] = r[lane];
    else if (lane < 8) g_adst[node * 4 + lane - 4] = r[lane];
}

// ---------------- GAT softmax + aggregation: 4 nodes/block x 64 thr, fp16 gathers ----------------
__device__ __forceinline__ float lrelu(float e) { return e > 0.f ? e : 0.2f * e; }

__device__ __forceinline__ float4 wmax4(float4 v) {
#pragma unroll
    for (int o = 16; o > 0; o >>= 1) {
        v.x = fmaxf(v.x, __shfl_xor_sync(0xffffffffu, v.x, o));
        v.y = fmaxf(v.y, __shfl_xor_sync(0xffffffffu, v.y, o));
        v.z = fmaxf(v.z, __shfl_xor_sync(0xffffffffu, v.z, o));
        v.w = fmaxf(v.w, __shfl_xor_sync(0xffffffffu, v.w, o));
    }
    return v;
}

__device__ __forceinline__ float4 wsum4(float4 v) {
#pragma unroll
    for (int o = 16; o > 0; o >>= 1) {
        v.x += __shfl_xor_sync(0xffffffffu, v.x, o);
        v.y += __shfl_xor_sync(0xffffffffu, v.y, o);
        v.z += __shfl_xor_sync(0xffffffffu, v.z, o);
        v.w += __shfl_xor_sync(0xffffffffu, v.w, o);
    }
    return v;
}

__global__ void __launch_bounds__(256) k_gat_agg(const float* __restrict__ bg, int n) {
    int tid = threadIdx.x;
    int g = tid >> 6, t = tid & 63;
    int h = t >> 4;
    int wig = (t >> 5) & 1;
    int lane = tid & 31;
    int node = blockIdx.x * 4 + g;
    bool valid = node < n;

    __shared__ float4 s_ex4[4][64];
    __shared__ int    s_srcv[4][64];
    __shared__ float4 s_red[4][2];

    int beg = 0, m = 0;
    if (valid) { beg = g_rowptr[node]; m = g_rowptr[node + 1] - beg + 1; }

    float4 ad = valid ? ((const float4*)g_adst)[node] : make_float4(0, 0, 0, 0);

    float4 mx = make_float4(-1e30f, -1e30f, -1e30f, -1e30f);
    for (int j = t; j < m; j += 64) {
        int s = (j < m - 1) ? g_epack[beg + j].x : node;
        float4 as = ((const float4*)g_asrc)[s];
        mx.x = fmaxf(mx.x, lrelu(as.x + ad.x));
        mx.y = fmaxf(mx.y, lrelu(as.y + ad.y));
        mx.z = fmaxf(mx.z, lrelu(as.z + ad.z));
        mx.w = fmaxf(mx.w, lrelu(as.w + ad.w));
    }
    mx = wmax4(mx);
    if (lane == 0) s_red[g][wig] = mx;
    __syncthreads();
    {
        float4 a = s_red[g][0], b2 = s_red[g][1];
        mx.x = fmaxf(a.x, b2.x); mx.y = fmaxf(a.y, b2.y);
        mx.z = fmaxf(a.z, b2.z); mx.w = fmaxf(a.w, b2.w);
    }

    float4 acc = make_float4(0, 0, 0, 0);
    float4 den = make_float4(0, 0, 0, 0);
    int ntiles = (m + 63) / 64;
    __shared__ int s_nt[4];
    if (t == 0) s_nt[g] = ntiles;
    __syncthreads();
    int ntmax = max(max(s_nt[0], s_nt[1]), max(s_nt[2], s_nt[3]));

    const uint2* hgq = (const uint2*)g_hg;
    const float* s_exf = (const float*)&s_ex4[0][0];
    for (int tile = 0; tile < ntmax; ++tile) {
        __syncthreads();
        int j = tile * 64 + t;
        if (j < m) {
            int s = (j < m - 1) ? g_epack[beg + j].x : node;
            s_srcv[g][t] = s;
            float4 as = ((const float4*)g_asrc)[s];
            float4 ex;
            ex.x = __expf(lrelu(as.x + ad.x) - mx.x);
            ex.y = __expf(lrelu(as.y + ad.y) - mx.y);
            ex.z = __expf(lrelu(as.z + ad.z) - mx.z);
            ex.w = __expf(lrelu(as.w + ad.w) - mx.w);
            den.x += ex.x; den.y += ex.y; den.z += ex.z; den.w += ex.w;
            s_ex4[g][t] = ex;
        }
        __syncthreads();
        int tcnt = min(64, m - tile * 64);
#pragma unroll 4
        for (int jj = 0; jj < tcnt; ++jj) {
            float exv = s_exf[g * 256 + jj * 4 + h];
            uint2 raw = hgq[(unsigned)s_srcv[g][jj] * 64u + t];
            float2 f0 = __half22float2(*(const __half2*)&raw.x);
            float2 f1 = __half22float2(*(const __half2*)&raw.y);
            acc.x += exv * f0.x; acc.y += exv * f0.y;
            acc.z += exv * f1.x; acc.w += exv * f1.y;
        }
    }
    den = wsum4(den);
    if (lane == 0) s_red[g][wig] = den;
    __syncthreads();
    float4 d0 = s_red[g][0], d1 = s_red[g][1];
    float4 dt = make_float4(d0.x + d1.x, d0.y + d1.y, d0.z + d1.z, d0.w + d1.w);
    float denh = (h == 0) ? dt.x : (h == 1) ? dt.y : (h == 2) ? dt.z : dt.w;
    if (valid) {
        float4 bgv = ((const float4*)bg)[t];
        float inv = 1.f / (denh + 1e-16f);
        float4 o;
        o.x = acc.x * inv + bgv.x; o.y = acc.y * inv + bgv.y;
        o.z = acc.z * inv + bgv.z; o.w = acc.w * inv + bgv.w;
        ((float4*)g_hatt)[(unsigned)node * 64u + t] = o;
    }
}

// ---------------- classifier: tiled SGEMM (64 nodes x 64 cols, K=256) + log_softmax ----------------
__global__ void __launch_bounds__(256) k_classifier(
    const float* __restrict__ wc1, const float* __restrict__ bc1,
    const float* __restrict__ wc2, const float* __restrict__ bc2,
    float* __restrict__ out, int n) {
    extern __shared__ float sm[];
    float* sW = sm;            // [256][64]
    float* sA = sm + 16384;    // [64][256] (reused as sZ [64][65])
    __shared__ float sWc2[192];
    __shared__ float sB[64];
    __shared__ float sB2[3];
    __shared__ float sLg[192];
    __shared__ float sLse[64];

    int tid = threadIdx.x;
    int base = blockIdx.x * 64;

    for (int i = tid; i < 4096; i += 256) ((float4*)sW)[i] = ((const float4*)wc1)[i];
    if (tid < 192) sWc2[tid] = wc2[tid];
    if (tid < 64) sB[tid] = bc1[tid];
    if (tid < 3) sB2[tid] = bc2[tid];

    const float4* hatt4 = (const float4*)g_hatt;
    for (int i = tid; i < 4096; i += 256) {
        int r = i >> 6;
        float4 v = make_float4(0, 0, 0, 0);
        if (base + r < n) v = hatt4[(unsigned)(base + r) * 64u + (i & 63)];
        ((float4*)sA)[i] = v;
    }
    __syncthreads();

    int colq = tid & 15;
    int nodeq = tid >> 4;
    float az[4][4];
#pragma unroll
    for (int i = 0; i < 4; ++i)
#pragma unroll
        for (int c = 0; c < 4; ++c) az[i][c] = 0.f;

    const float4* sW4 = (const float4*)sW;
#pragma unroll 4
    for (int k = 0; k < 256; ++k) {
        float a0 = sA[(nodeq * 4 + 0) * 256 + k];
        float a1 = sA[(nodeq * 4 + 1) * 256 + k];
        float a2 = sA[(nodeq * 4 + 2) * 256 + k];
        float a3 = sA[(nodeq * 4 + 3) * 256 + k];
        float4 wv = sW4[k * 16 + colq];
        az[0][0] += a0 * wv.x; az[0][1] += a0 * wv.y; az[0][2] += a0 * wv.z; az[0][3] += a0 * wv.w;
        az[1][0] += a1 * wv.x; az[1][1] += a1 * wv.y; az[1][2] += a1 * wv.z; az[1][3] += a1 * wv.w;
        az[2][0] += a2 * wv.x; az[2][1] += a2 * wv.y; az[2][2] += a2 * wv.z; az[2][3] += a2 * wv.w;
        az[3][0] += a3 * wv.x; az[3][1] += a3 * wv.y; az[3][2] += a3 * wv.z; az[3][3] += a3 * wv.w;
    }
    __syncthreads();
    float* sZ = sA;
#pragma unroll
    for (int i = 0; i < 4; ++i)
#pragma unroll
        for (int c = 0; c < 4; ++c)
            sZ[(nodeq * 4 + i) * 65 + colq * 4 + c] = fmaxf(az[i][c] + sB[colq * 4 + c], 0.f);
    __syncthreads();

    if (tid < 192) {
        int r = tid / 3, o = tid - 3 * r;
        float a = sB2[o];
#pragma unroll 8
        for (int c = 0; c < 64; ++c) a += sZ[r * 65 + c] * sWc2[c * 3 + o];
        sLg[tid] = a;
    }
    __syncthreads();
    if (tid < 64) {
        float l0 = sLg[tid * 3 + 0], l1 = sLg[tid * 3 + 1], l2 = sLg[tid * 3 + 2];
        float mm = fmaxf(l0, fmaxf(l1, l2));
        sLse[tid] = mm + logf(__expf(l0 - mm) + __expf(l1 - mm) + __expf(l2 - mm));
    }
    __syncthreads();
    int nvalid = n - base; if (nvalid > 64) nvalid = 64;
    if (tid < nvalid * 3) out[base * 3 + tid] = sLg[tid] - sLse[tid / 3];
}

// ---------------- launch ----------------
extern "C" void kernel_launch(void* const* d_in, const int* in_sizes, int n_in,
                              void* d_out, int out_size) {
    const float* x     = (const float*)d_in[0];
    const void*  ei    = (const void*)d_in[1];
    const float* w1    = (const float*)d_in[2];
    const float* b1    = (const float*)d_in[3];
    const float* w2    = (const float*)d_in[4];
    const float* b2    = (const float*)d_in[5];
    const float* w3    = (const float*)d_in[6];
    const float* b3    = (const float*)d_in[7];
    const float* wg    = (const float*)d_in[8];
    const float* bg    = (const float*)d_in[9];
    const float* att_s = (const float*)d_in[10];
    const float* att_d = (const float*)d_in[11];
    const float* wc1   = (const float*)d_in[12];
    const float* bc1   = (const float*)d_in[13];
    const float* wc2   = (const float*)d_in[14];
    const float* bc2   = (const float*)d_in[15];
    float* out = (float*)d_out;

    int n = in_sizes[0] / 8;
    int e = in_sizes[1] / 2;

    int nb512 = (n + 511) / 512;

    k_detect<<<1, 1>>>((const int*)ei);
    k_zero<<<(n + 255) / 256, 256>>>(n);
    k_count<<<(e + 255) / 256, 256>>>(ei, e);
    k_scan1<<<nb512, 512>>>(n);
    k_scan2<<<1, 1>>>(nb512);
    k_scan3<<<(n + 255) / 256, 256>>>(n, e);
    k_scatter<<<(e + 255) / 256, 256>>>(ei, e);

    int gs = 444;

    // GCN layer 1
    k_gemm8<<<(n + 3) / 4, 256>>>(x, w1, n);
    k_gcn_agg<<<(n + 7) / 8, 256>>>(b1, n, 0);
    // GCN layer 2 (residual)
    k_gemm64<<<gs, 256>>>(w2, n);
    k_gcn_agg<<<(n + 7) / 8, 256>>>(b2, n, 1);
    // GCN layer 3 (residual)
    k_gemm64<<<gs, 256>>>(w3, n);
    k_gcn_agg<<<(n + 7) / 8, 256>>>(b3, n, 1);
    // GAT
    k_att_pre<<<1, 512>>>(wg, att_s, att_d);
    k_gat_gemm<<<gs, 256>>>(wg, n);
    k_att<<<(n + 7) / 8, 256>>>(n);
    k_gat_agg<<<(n + 3) / 4, 256>>>(bg, n);
    // classifier (131072 B dynamic smem)
    static int smem_set = 0;
    if (!smem_set) {
        cudaFuncSetAttribute(k_classifier, cudaFuncAttributeMaxDynamicSharedMemorySize, 135168);
        smem_set = 1;
    }
    k_classifier<<<(n + 63) / 64, 256, 131072>>>(wc1, bc1, wc2, bc2, out, n);
}

// round 11
// speedup vs baseline: 1.3137x; 1.2253x over previous
#include <cuda_runtime.h>
#include <cuda_fp16.h>
#include <math.h>

#define NN 100000
#define EE 1600000

// ---------------- device scratch (no allocations allowed) ----------------
__device__ int   g_is64;
__device__ int   g_count[NN];
__device__ int   g_rowptr[NN + 1];
__device__ int   g_cursor[NN];
__device__ int   g_blocksums[256];
__device__ float g_dinv[NN];
__device__ int2  g_epack[EE];              // (src, norm bits)
__device__ __half g_hlin[NN * 64];         // fp16 GCN linear output (12.8MB)
__device__ float g_h[NN * 64];             // fp32 residual stream
__device__ __half g_h16[NN * 64];          // fp16 copy of final h for GAT gathers
__device__ __half g_hagg[NN * 256];        // fp16 per-head aggregated h (51MB)
__device__ float g_asrc[NN * 4];
__device__ float g_adst[NN * 4];
__device__ float g_Wa[64 * 8];             // composite att weights
__device__ float g_Wcomb[256 * 64];        // folded wg∘wc1
__device__ float g_const[64];              // folded bc1 + bg∘wc1

__device__ __forceinline__ int ld_edge(const void* ei, int is64, long long idx) {
    if (is64) return (int)((const long long*)ei)[idx];
    return ((const int*)ei)[idx];
}

// ---------------- dtype detection ----------------
__global__ void k_detect(const int* __restrict__ ei) {
    int all0 = 1;
    for (int i = 1; i < 32; i += 2)
        if (ei[i] != 0) { all0 = 0; break; }
    g_is64 = all0;
}

// ---------------- CSR build ----------------
__global__ void k_zero(int n) {
    int i = blockIdx.x * blockDim.x + threadIdx.x;
    if (i < n) g_count[i] = 0;
}

__global__ void k_count(const void* __restrict__ ei, int e) {
    int i = blockIdx.x * blockDim.x + threadIdx.x;
    if (i < e) {
        int is64 = g_is64;
        int d = ld_edge(ei, is64, (long long)e + i);
        atomicAdd(&g_count[d], 1);
    }
}

__global__ void k_scan1(int n) {
    __shared__ int s[512];
    int tid = threadIdx.x;
    int i = blockIdx.x * 512 + tid;
    int v = (i < n) ? g_count[i] : 0;
    s[tid] = v;
    __syncthreads();
    for (int off = 1; off < 512; off <<= 1) {
        int t = (tid >= off) ? s[tid - off] : 0;
        __syncthreads();
        s[tid] += t;
        __syncthreads();
    }
    if (i < n) g_rowptr[i] = s[tid] - v;
    if (tid == 511) g_blocksums[blockIdx.x] = s[511];
}

__global__ void k_scan2(int nb) {
    int run = 0;
    for (int b = 0; b < nb; ++b) { int t = g_blocksums[b]; g_blocksums[b] = run; run += t; }
}

__global__ void k_scan3(int n, int e) {
    int i = blockIdx.x * blockDim.x + threadIdx.x;
    if (i < n) {
        int rp = g_rowptr[i] + g_blocksums[i >> 9];
        g_rowptr[i] = rp;
        g_cursor[i] = rp;
        g_dinv[i] = rsqrtf((float)(g_count[i] + 1));
        if (i == 0) g_rowptr[n] = e;
    }
}

__global__ void k_scatter(const void* __restrict__ ei, int e) {
    int i = blockIdx.x * blockDim.x + threadIdx.x;
    if (i < e) {
        int is64 = g_is64;
        int s = ld_edge(ei, is64, i);
        int d = ld_edge(ei, is64, (long long)e + i);
        int p = atomicAdd(&g_cursor[d], 1);
        g_epack[p] = make_int2(s, __float_as_int(g_dinv[s] * g_dinv[d]));
    }
}

// ---------------- layer-1 GEMM: hlin = X[N,8] @ W[8,64] (fp16 out) ----------------
__global__ void k_gemm8(const float* __restrict__ X, const float* __restrict__ W, int n) {
    __shared__ float sx[4][8];
    int tid = threadIdx.x;
    int l = tid >> 6, col = tid & 63;
    int base = blockIdx.x * 4;
    if (tid < 32) {
        int r = base + (tid >> 3);
        sx[tid >> 3][tid & 7] = (r < n) ? X[r * 8 + (tid & 7)] : 0.f;
    }
    __syncthreads();
    int node = base + l;
    if (node < n) {
        float acc = 0.f;
#pragma unroll
        for (int k = 0; k < 8; ++k) acc += sx[l][k] * W[k * 64 + col];
        g_hlin[node * 64 + col] = __float2half(acc);
    }
}

// ---------------- GCN GEMM: hlin = g_h @ W[64,64], scalar W col in regs ----------------
__global__ void __launch_bounds__(256) k_gemm64(const float* __restrict__ W, int n) {
    float w[64];
    int tid = threadIdx.x;
    int l = tid >> 6, col = tid & 63;
#pragma unroll
    for (int k = 0; k < 64; ++k) w[k] = W[k * 64 + col];
    __shared__ float sx[4][64];
    for (int base = blockIdx.x * 4; base < n; base += gridDim.x * 4) {
        __syncthreads();
        int r = base + (tid >> 6);
        sx[tid >> 6][tid & 63] = (r < n) ? g_h[r * 64 + (tid & 63)] : 0.f;
        __syncthreads();
        int node = base + l;
        if (node < n) {
            float acc = 0.f;
#pragma unroll
            for (int k = 0; k < 64; ++k) acc += sx[l][k] * w[k];
            g_hlin[node * 64 + col] = __float2half(acc);
        }
    }
}

// ---------------- GCN aggregation: warp/node, fp16 gathers, 8-deep prefetch ----------------
__global__ void k_gcn_agg(const float* __restrict__ b, int n, int residual) {
    int tid = threadIdx.x, warp = tid >> 5, lane = tid & 31;
    int node = blockIdx.x * 8 + warp;
    if (node >= n) return;
    float di = g_dinv[node];
    float2 self = __half22float2(*(const __half2*)&g_hlin[node * 64 + 2 * lane]);
    float accx = di * di * self.x, accy = di * di * self.y;
    int beg = g_rowptr[node], end = g_rowptr[node + 1];
    int j = beg;
    for (; j + 7 < end; j += 8) {
        int2 ep[8];
#pragma unroll
        for (int q = 0; q < 8; ++q) ep[q] = g_epack[j + q];
#pragma unroll
        for (int q = 0; q < 8; ++q) {
            float w = __int_as_float(ep[q].y);
            float2 v = __half22float2(*(const __half2*)&g_hlin[ep[q].x * 64 + 2 * lane]);
            accx += w * v.x; accy += w * v.y;
        }
    }
    for (; j < end; ++j) {
        int2 ep = g_epack[j];
        float w = __int_as_float(ep.y);
        float2 v = __half22float2(*(const __half2*)&g_hlin[ep.x * 64 + 2 * lane]);
        accx += w * v.x; accy += w * v.y;
    }
    float2 bb = ((const float2*)b)[lane];
    float vx = fmaxf(accx + bb.x, 0.f), vy = fmaxf(accy + bb.y, 0.f);
    float2* H = (float2*)g_h;
    if (residual) {
        float2 p = H[node * 32 + lane];
        H[node * 32 + lane] = make_float2(p.x + vx, p.y + vy);
    } else {
        H[node * 32 + lane] = make_float2(vx, vy);
    }
}

// ---------------- composite attention weights: Wa = wg . att  (64x8) ----------------
__global__ void k_att_pre(const float* __restrict__ wg,
                          const float* __restrict__ att_s,
                          const float* __restrict__ att_d) {
    int t = threadIdx.x;       // 512 threads: o=t&7, k=t>>3
    int o = t & 7, k = t >> 3;
    int h = o & 3;
    const float* att = (o < 4) ? att_s : att_d;
    float s = 0.f;
#pragma unroll 8
    for (int c = 0; c < 64; ++c) s += wg[k * 256 + h * 64 + c] * att[h * 64 + c];
    g_Wa[k * 8 + o] = s;
}

// ---------------- folded classifier weights: Wcomb[(h,k)][c] = sum_j wg[k][h64+j] wc1[h64+j][c] ----------------
__global__ void k_wcomb(const float* __restrict__ wg, const float* __restrict__ wc1) {
    int c = threadIdx.x;          // 64
    int hk = blockIdx.x;          // 256
    int h = hk >> 6, k = hk & 63;
    float s = 0.f;
#pragma unroll 8
    for (int j = 0; j < 64; ++j)
        s += wg[k * 256 + h * 64 + j] * wc1[(h * 64 + j) * 64 + c];
    g_Wcomb[hk * 64 + c] = s;
}

__global__ void k_const(const float* __restrict__ wc1, const float* __restrict__ bc1,
                        const float* __restrict__ bg) {
    int c = threadIdx.x;  // 64
    float s = bc1[c];
#pragma unroll 8
    for (int q = 0; q < 256; ++q) s += bg[q] * wc1[q * 64 + c];
    g_const[c] = s;
}

// ---------------- attention coeffs + fp16 h copy (warp per node) ----------------
__global__ void k_att(int n) {
    int tid = threadIdx.x, warp = tid >> 5, lane = tid & 31;
    int node = blockIdx.x * 8 + warp;
    if (node >= n) return;
    float2 hv = *(const float2*)&g_h[node * 64 + 2 * lane];
    ((__half2*)g_h16)[node * 32 + lane] = __floats2half2_rn(hv.x, hv.y);
    float r[8];
#pragma unroll
    for (int o = 0; o < 8; ++o) {
        r[o] = hv.x * g_Wa[(2 * lane) * 8 + o] + hv.y * g_Wa[(2 * lane + 1) * 8 + o];
#pragma unroll
        for (int off = 16; off > 0; off >>= 1)
            r[o] += __shfl_xor_sync(0xffffffffu, r[o], off);
    }
    if (lane < 4)      g_asrc[node * 4 + lane] = r[lane];
    else if (lane < 8) g_adst[node * 4 + lane - 4] = r[lane];
}

// ---------------- GAT softmax + 64-dim aggregation (linearity fold) ----------------
__device__ __forceinline__ float lrelu(float e) { return e > 0.f ? e : 0.2f * e; }

__device__ __forceinline__ float4 wmax4(float4 v) {
#pragma unroll
    for (int o = 16; o > 0; o >>= 1) {
        v.x = fmaxf(v.x, __shfl_xor_sync(0xffffffffu, v.x, o));
        v.y = fmaxf(v.y, __shfl_xor_sync(0xffffffffu, v.y, o));
        v.z = fmaxf(v.z, __shfl_xor_sync(0xffffffffu, v.z, o));
        v.w = fmaxf(v.w, __shfl_xor_sync(0xffffffffu, v.w, o));
    }
    return v;
}

__device__ __forceinline__ float4 wsum4(float4 v) {
#pragma unroll
    for (int o = 16; o > 0; o >>= 1) {
        v.x += __shfl_xor_sync(0xffffffffu, v.x, o);
        v.y += __shfl_xor_sync(0xffffffffu, v.y, o);
        v.z += __shfl_xor_sync(0xffffffffu, v.z, o);
        v.w += __shfl_xor_sync(0xffffffffu, v.w, o);
    }
    return v;
}

__global__ void __launch_bounds__(256) k_gat_agg2(int n) {
    int tid = threadIdx.x;
    int g = tid >> 6, t = tid & 63;
    int wig = (t >> 5) & 1;
    int lane = tid & 31;
    int node = blockIdx.x * 4 + g;
    bool valid = node < n;

    __shared__ float4 s_ex4[4][64];
    __shared__ int    s_srcv[4][64];
    __shared__ float4 s_red[4][2];
    __shared__ float2 s_part[4][4][32];   // warp-1 partials: [group][head][lane]
    __shared__ int    s_nt[4];

    int beg = 0, m = 0;
    if (valid) { beg = g_rowptr[node]; m = g_rowptr[node + 1] - beg + 1; }

    float4 ad = valid ? ((const float4*)g_adst)[node] : make_float4(0, 0, 0, 0);

    // pass 1: per-head max
    float4 mx = make_float4(-1e30f, -1e30f, -1e30f, -1e30f);
    for (int j = t; j < m; j += 64) {
        int s = (j < m - 1) ? g_epack[beg + j].x : node;
        float4 as = ((const float4*)g_asrc)[s];
        mx.x = fmaxf(mx.x, lrelu(as.x + ad.x));
        mx.y = fmaxf(mx.y, lrelu(as.y + ad.y));
        mx.z = fmaxf(mx.z, lrelu(as.z + ad.z));
        mx.w = fmaxf(mx.w, lrelu(as.w + ad.w));
    }
    mx = wmax4(mx);
    if (lane == 0) s_red[g][wig] = mx;
    if (t == 0) s_nt[g] = (m + 63) >> 6;
    __syncthreads();
    {
        float4 a = s_red[g][0], b2 = s_red[g][1];
        mx.x = fmaxf(a.x, b2.x); mx.y = fmaxf(a.y, b2.y);
        mx.z = fmaxf(a.z, b2.z); mx.w = fmaxf(a.w, b2.w);
    }
    int ntmax = max(max(s_nt[0], s_nt[1]), max(s_nt[2], s_nt[3]));

    float2 acc0 = make_float2(0, 0), acc1 = make_float2(0, 0);
    float2 acc2 = make_float2(0, 0), acc3 = make_float2(0, 0);
    float4 den = make_float4(0, 0, 0, 0);
    const __half2* h2p = (const __half2*)g_h16;

    for (int tile = 0; tile < ntmax; ++tile) {
        __syncthreads();
        int j = tile * 64 + t;
        if (j < m) {
            int s = (j < m - 1) ? g_epack[beg + j].x : node;
            s_srcv[g][t] = s;
            float4 as = ((const float4*)g_asrc)[s];
            float4 ex;
            ex.x = __expf(lrelu(as.x + ad.x) - mx.x);
            ex.y = __expf(lrelu(as.y + ad.y) - mx.y);
            ex.z = __expf(lrelu(as.z + ad.z) - mx.z);
            ex.w = __expf(lrelu(as.w + ad.w) - mx.w);
            den.x += ex.x; den.y += ex.y; den.z += ex.z; den.w += ex.w;
            s_ex4[g][t] = ex;
        }
        __syncthreads();
        int cnt = min(64, m - tile * 64);      // may be <= 0 for finished groups
        int lo = wig * 32;
        int myn = min(32, cnt - lo);
#pragma unroll 4
        for (int jj = 0; jj < myn; ++jj) {
            int idx = lo + jj;
            int s = s_srcv[g][idx];
            float4 e4 = s_ex4[g][idx];
            float2 hv = __half22float2(h2p[(unsigned)s * 32u + lane]);
            acc0.x += e4.x * hv.x; acc0.y += e4.x * hv.y;
            acc1.x += e4.y * hv.x; acc1.y += e4.y * hv.y;
            acc2.x += e4.z * hv.x; acc2.y += e4.z * hv.y;
            acc3.x += e4.w * hv.x; acc3.y += e4.w * hv.y;
        }
    }
    den = wsum4(den);
    if (lane == 0) s_red[g][wig] = den;
    if (wig == 1) {
        s_part[g][0][lane] = acc0; s_part[g][1][lane] = acc1;
        s_part[g][2][lane] = acc2; s_part[g][3][lane] = acc3;
    }
    __syncthreads();
    if (wig == 0 && valid) {
        float4 d0 = s_red[g][0], d1 = s_red[g][1];
        float4 dt = make_float4(d0.x + d1.x, d0.y + d1.y, d0.z + d1.z, d0.w + d1.w);
        float i0 = 1.f / (dt.x + 1e-16f), i1 = 1.f / (dt.y + 1e-16f);
        float i2 = 1.f / (dt.z + 1e-16f), i3 = 1.f / (dt.w + 1e-16f);
        float2 p0 = s_part[g][0][lane], p1 = s_part[g][1][lane];
        float2 p2 = s_part[g][2][lane], p3 = s_part[g][3][lane];
        __half2* out = (__half2*)g_hagg;
        unsigned rb = (unsigned)node * 128u;
        out[rb + 0 * 32 + lane] = __floats2half2_rn((acc0.x + p0.x) * i0, (acc0.y + p0.y) * i0);
        out[rb + 1 * 32 + lane] = __floats2half2_rn((acc1.x + p1.x) * i1, (acc1.y + p1.y) * i1);
        out[rb + 2 * 32 + lane] = __floats2half2_rn((acc2.x + p2.x) * i2, (acc2.y + p2.y) * i2);
        out[rb + 3 * 32 + lane] = __floats2half2_rn((acc3.x + p3.x) * i3, (acc3.y + p3.y) * i3);
    }
}

// ---------------- classifier: relu(hagg@Wcomb + const) @ wc2 + bc2, log_softmax ----------------
__global__ void __launch_bounds__(256) k_classifier(
    const float* __restrict__ wc2, const float* __restrict__ bc2,
    float* __restrict__ out, int n) {
    extern __shared__ float sm[];
    float* sW = sm;            // [256][64]  (Wcomb)
    float* sA = sm + 16384;    // [64][256]  (reused as sZ [64][65])
    __shared__ float sWc2[192];
    __shared__ float sB[64];
    __shared__ float sB2[3];
    __shared__ float sLg[192];
    __shared__ float sLse[64];

    int tid = threadIdx.x;
    int base = blockIdx.x * 64;

    for (int i = tid; i < 4096; i += 256) ((float4*)sW)[i] = ((const float4*)g_Wcomb)[i];
    if (tid < 192) sWc2[tid] = wc2[tid];
    if (tid < 64) sB[tid] = g_const[tid];
    if (tid < 3) sB2[tid] = bc2[tid];

    const uint2* hagg2 = (const uint2*)g_hagg;   // 4 halves per uint2, 64 per row
    for (int i = tid; i < 4096; i += 256) {
        int r = i >> 6, c = i & 63;
        float4 v = make_float4(0, 0, 0, 0);
        if (base + r < n) {
            uint2 raw = hagg2[(unsigned)(base + r) * 64u + c];
            float2 f0 = __half22float2(*(const __half2*)&raw.x);
            float2 f1 = __half22float2(*(const __half2*)&raw.y);
            v = make_float4(f0.x, f0.y, f1.x, f1.y);
        }
        ((float4*)sA)[i] = v;
    }
    __syncthreads();

    int colq = tid & 15;
    int nodeq = tid >> 4;
    float az[4][4];
#pragma unroll
    for (int i = 0; i < 4; ++i)
#pragma unroll
        for (int c = 0; c < 4; ++c) az[i][c] = 0.f;

    const float4* sW4 = (const float4*)sW;
#pragma unroll 4
    for (int k = 0; k < 256; ++k) {
        float a0 = sA[(nodeq * 4 + 0) * 256 + k];
        float a1 = sA[(nodeq * 4 + 1) * 256 + k];
        float a2 = sA[(nodeq * 4 + 2) * 256 + k];
        float a3 = sA[(nodeq * 4 + 3) * 256 + k];
        float4 wv = sW4[k * 16 + colq];
        az[0][0] += a0 * wv.x; az[0][1] += a0 * wv.y; az[0][2] += a0 * wv.z; az[0][3] += a0 * wv.w;
        az[1][0] += a1 * wv.x; az[1][1] += a1 * wv.y; az[1][2] += a1 * wv.z; az[1][3] += a1 * wv.w;
        az[2][0] += a2 * wv.x; az[2][1] += a2 * wv.y; az[2][2] += a2 * wv.z; az[2][3] += a2 * wv.w;
        az[3][0] += a3 * wv.x; az[3][1] += a3 * wv.y; az[3][2] += a3 * wv.z; az[3][3] += a3 * wv.w;
    }
    __syncthreads();
    float* sZ = sA;
#pragma unroll
    for (int i = 0; i < 4; ++i)
#pragma unroll
        for (int c = 0; c < 4; ++c)
            sZ[(nodeq * 4 + i) * 65 + colq * 4 + c] = fmaxf(az[i][c] + sB[colq * 4 + c], 0.f);
    __syncthreads();

    if (tid < 192) {
        int r = tid / 3, o = tid - 3 * r;
        float a = sB2[o];
#pragma unroll 8
        for (int c = 0; c < 64; ++c) a += sZ[r * 65 + c] * sWc2[c * 3 + o];
        sLg[tid] = a;
    }
    __syncthreads();
    if (tid < 64) {
        float l0 = sLg[tid * 3 + 0], l1 = sLg[tid * 3 + 1], l2 = sLg[tid * 3 + 2];
        float mm = fmaxf(l0, fmaxf(l1, l2));
        sLse[tid] = mm + logf(__expf(l0 - mm) + __expf(l1 - mm) + __expf(l2 - mm));
    }
    __syncthreads();
    int nvalid = n - base; if (nvalid > 64) nvalid = 64;
    if (tid < nvalid * 3) out[base * 3 + tid] = sLg[tid] - sLse[tid / 3];
}

// ---------------- launch ----------------
extern "C" void kernel_launch(void* const* d_in, const int* in_sizes, int n_in,
                              void* d_out, int out_size) {
    const float* x     = (const float*)d_in[0];
    const void*  ei    = (const void*)d_in[1];
    const float* w1    = (const float*)d_in[2];
    const float* b1    = (const float*)d_in[3];
    const float* w2    = (const float*)d_in[4];
    const float* b2    = (const float*)d_in[5];
    const float* w3    = (const float*)d_in[6];
    const float* b3    = (const float*)d_in[7];
    const float* wg    = (const float*)d_in[8];
    const float* bg    = (const float*)d_in[9];
    const float* att_s = (const float*)d_in[10];
    const float* att_d = (const float*)d_in[11];
    const float* wc1   = (const float*)d_in[12];
    const float* bc1   = (const float*)d_in[13];
    const float* wc2   = (const float*)d_in[14];
    const float* bc2   = (const float*)d_in[15];
    float* out = (float*)d_out;

    int n = in_sizes[0] / 8;
    int e = in_sizes[1] / 2;

    int nb512 = (n + 511) / 512;

    k_detect<<<1, 1>>>((const int*)ei);
    k_zero<<<(n + 255) / 256, 256>>>(n);
    k_count<<<(e + 255) / 256, 256>>>(ei, e);
    k_scan1<<<nb512, 512>>>(n);
    k_scan2<<<1, 1>>>(nb512);
    k_scan3<<<(n + 255) / 256, 256>>>(n, e);
    k_scatter<<<(e + 255) / 256, 256>>>(ei, e);

    int gs = 444;

    // GCN layer 1
    k_gemm8<<<(n + 3) / 4, 256>>>(x, w1, n);
    k_gcn_agg<<<(n + 7) / 8, 256>>>(b1, n, 0);
    // GCN layer 2 (residual)
    k_gemm64<<<gs, 256>>>(w2, n);
    k_gcn_agg<<<(n + 7) / 8, 256>>>(b2, n, 1);
    // GCN layer 3 (residual)
    k_gemm64<<<gs, 256>>>(w3, n);
    k_gcn_agg<<<(n + 7) / 8, 256>>>(b3, n, 1);
    // GAT (folded): precomputes + att coeffs + 64-dim aggregation
    k_att_pre<<<1, 512>>>(wg, att_s, att_d);
    k_wcomb<<<256, 64>>>(wg, wc1);
    k_const<<<1, 64>>>(wc1, bc1, bg);
    k_att<<<(n + 7) / 8, 256>>>(n);
    k_gat_agg2<<<(n + 3) / 4, 256>>>(n);
    // classifier (folded Wcomb) — 131072 B dynamic smem
    static int smem_set = 0;
    if (!smem_set) {
        cudaFuncSetAttribute(k_classifier, cudaFuncAttributeMaxDynamicSharedMemorySize, 135168);
        smem_set = 1;
    }
    k_classifier<<<(n + 63) / 64, 256, 131072>>>(wc2, bc2, out, n);
}